// round 7
// baseline (speedup 1.0000x reference)
#include <cuda_runtime.h>
#include <cuda_bf16.h>

#define NN 5
#define BB 8
#define CC 256
#define HWD 1024
#define KH 512            // stored K per operand: [hi(256) | lo(256)]
#define NCH 12            // chunks: (Ahi,Bhi)x4, (Ahi,Blo)x4, (Alo,Bhi)x4
#define KC 64             // k per chunk
#define TM 64             // CTA o-tile
#define TPX 64            // CTA pixel-tile
#define THREADS 256

// A operands [i][o][k2] (k2: 0-255 hi, 256-511 lo), k-contiguous (row-major for MMA A)
__device__ __align__(16) __nv_bfloat16 g_Am[NN * CC * KH];
__device__ __align__(16) __nv_bfloat16 g_Aw[NN * CC * KH];
// B operand  [j][b][p][k2], k-contiguous (n-major rows -> col-major fragments)
__device__ __align__(16) __nv_bfloat16 g_X[NN * BB * HWD * KH];

__global__ void prep_w(const float* __restrict__ w) {
    int idx = blockIdx.x * blockDim.x + threadIdx.x;   // (i*CC+o)*KH + k2
    if (idx >= NN * CC * KH) return;
    int k2 = idx & (KH - 1);
    int oi = idx >> 9;
    int o = oi & 255, i = oi >> 8;
    int k = k2 & 255, lo = k2 >> 8;
    const float* row = w + (size_t)(i * CC + o) * (2 * CC);
    float w2 = row[CC + k];
    float m  = row[k] + w2;
    __nv_bfloat16 mh = __float2bfloat16_rn(m);
    __nv_bfloat16 wh = __float2bfloat16_rn(w2);
    g_Am[idx] = lo ? __float2bfloat16_rn(m  - __bfloat162float(mh)) : mh;
    g_Aw[idx] = lo ? __float2bfloat16_rn(w2 - __bfloat162float(wh)) : wh;
}

// Transpose [k][p] -> [p][k] with hi/lo split, via smem tile (32k x 128p).
__global__ __launch_bounds__(256) void prep_x(const float* __restrict__ x) {
    __shared__ float s[32][129];
    // grid.x = jb(40) * ktile(8) * ptile(8)
    int bid = blockIdx.x;
    int pt = bid & 7, kt = (bid >> 3) & 7, jb = bid >> 6;
    int k0 = kt * 32, p0 = pt * 128;
    int tid = threadIdx.x;
    #pragma unroll
    for (int t = 0; t < 16; t++) {
        int idx = tid + t * 256;
        int kk = idx >> 7, pp = idx & 127;
        s[kk][pp] = x[((size_t)jb * CC + k0 + kk) * HWD + p0 + pp];
    }
    __syncthreads();
    int pp = tid & 127, part = tid >> 7;           // part: 0=hi, 1=lo
    __nv_bfloat16* dst = g_X + ((size_t)jb * HWD + p0 + pp) * KH + part * 256 + k0;
    #pragma unroll
    for (int kk = 0; kk < 32; kk += 2) {
        float v0 = s[kk][pp], v1 = s[kk + 1][pp];
        __nv_bfloat16 h0 = __float2bfloat16_rn(v0);
        __nv_bfloat16 h1 = __float2bfloat16_rn(v1);
        __nv_bfloat162 o2;
        if (part) {
            o2.x = __float2bfloat16_rn(v0 - __bfloat162float(h0));
            o2.y = __float2bfloat16_rn(v1 - __bfloat162float(h1));
        } else {
            o2.x = h0; o2.y = h1;
        }
        *(__nv_bfloat162*)(dst + kk) = o2;
    }
}

// ---- smem: stage = A_M(8K) | A_W(8K) | B[5](40K) = 56KB, double buffered ----
#define STG 57344
#define OFF_AW 8192
#define OFF_B 16384
struct SmemT { char st[2][STG]; };

#define LDM4(r, a) \
    asm volatile("ldmatrix.sync.aligned.m8n8.x4.shared.b16 {%0,%1,%2,%3}, [%4];" \
        : "=r"((r)[0]), "=r"((r)[1]), "=r"((r)[2]), "=r"((r)[3]) : "r"(a))

#define MMA(d, a, b0, b1) \
    asm volatile("mma.sync.aligned.m16n8k16.row.col.f32.bf16.bf16.f32 " \
        "{%0,%1,%2,%3}, {%4,%5,%6,%7}, {%8,%9}, {%0,%1,%2,%3};" \
        : "+f"((d)[0]), "+f"((d)[1]), "+f"((d)[2]), "+f"((d)[3]) \
        : "r"((a)[0]), "r"((a)[1]), "r"((a)[2]), "r"((a)[3]), "r"(b0), "r"(b1))

__global__ __launch_bounds__(THREADS, 1) void fused_kernel(
    const float* __restrict__ x,
    const float* __restrict__ bias,
    float* __restrict__ out)
{
    extern __shared__ __align__(16) char smem_raw[];
    SmemT& sm = *reinterpret_cast<SmemT*>(smem_raw);

    const int i  = blockIdx.z;
    const int o0 = blockIdx.y * TM;
    const int b  = blockIdx.x >> 4;
    const int p0 = (blockIdx.x & 15) * TPX;

    const int tid  = threadIdx.x;
    const int lane = tid & 31;
    const int wid  = tid >> 5;
    const int wo = (wid >> 1) * 16;            // warp o offset (0..48)
    const int wn = (wid & 1) * 32;             // warp px offset (0/32)
    const unsigned smem_base = (unsigned)__cvta_generic_to_shared(&sm);

    // per-thread ldmatrix row geometry (swizzle term is (lane&7)<<4 for all)
    const int sw7   = (lane & 7) << 4;
    const int arow  = wo + ((lane >> 3) & 1) * 8 + (lane & 7);
    const int a16   = (lane >> 4) * 16;        // k-half select for A
    const int brow0 = wn + (lane >> 4) * 8 + (lane & 7);
    const int b16   = ((lane >> 3) & 1) * 16;  // k-half select for B

    float acc[6][4][4];
    #pragma unroll
    for (int m = 0; m < 6; m++)
        #pragma unroll
        for (int g = 0; g < 4; g++)
            #pragma unroll
            for (int e = 0; e < 4; e++) acc[m][g][e] = 0.f;

    auto load_chunk = [&](int c, int s) {
        const int ka = (c < 8) ? (c & 3) * KC : 256 + (c - 8) * KC;
        const int kb = (c < 4) ? c * KC : (c < 8 ? 256 + (c - 4) * KC : (c - 8) * KC);
        char* stg = sm.st[s];
        #pragma unroll
        for (int t = 0; t < 14; t++) {
            int q = tid + t * THREADS;
            const __nv_bfloat16* src;
            int doff;
            if (q < 1024) {                      // A tiles: M(q<512), W
                int mat = q >> 9, idx = q & 511, row = idx >> 3, c16 = idx & 7;
                const __nv_bfloat16* g = mat ? g_Aw : g_Am;
                src = g + (size_t)(i * CC + o0 + row) * KH + ka + c16 * 8;
                doff = mat * OFF_AW + row * 128 + ((c16 << 4) ^ ((row & 7) << 4));
            } else {                             // B tiles: 5 x [64p][64k]
                int q2 = q - 1024;
                int j = q2 >> 9, idx = q2 & 511, row = idx >> 3, c16 = idx & 7;
                src = g_X + (size_t)((j * BB + b) * HWD + p0 + row) * KH + kb + c16 * 8;
                doff = OFF_B + j * 8192 + row * 128 + ((c16 << 4) ^ ((row & 7) << 4));
            }
            unsigned ds = (unsigned)__cvta_generic_to_shared(stg + doff);
            asm volatile("cp.async.cg.shared.global [%0], [%1], 16;"
                         :: "r"(ds), "l"(src));
        }
        asm volatile("cp.async.commit_group;");
    };

    load_chunk(0, 0);

    for (int c = 0; c < NCH; c++) {
        asm volatile("cp.async.wait_group 0;");
        __syncthreads();
        if (c < NCH - 1) load_chunk(c + 1, (c + 1) & 1);
        const unsigned stq = smem_base + (unsigned)((c & 1) * STG);

        #pragma unroll
        for (int kk4 = 0; kk4 < 4; kk4++) {
            const int kko = kk4 * 32;            // k16-step byte offset
            unsigned aM[4], aW[4];
            {
                unsigned aa = stq + arow * 128 + (unsigned)((kko + a16) ^ sw7);
                LDM4(aM, aa);
                LDM4(aW, aa + OFF_AW);
            }
            unsigned bf[5][8];
            #pragma unroll
            for (int j = 0; j < NN; j++) {
                unsigned bb0 = stq + OFF_B + j * 8192 + brow0 * 128
                             + (unsigned)((kko + b16) ^ sw7);
                LDM4(&bf[j][0], bb0);            // n 0-15: g0 (b0,b1), g1 (b0,b1)
                LDM4(&bf[j][4], bb0 + 16 * 128); // n 16-31: g2, g3
            }
            #pragma unroll
            for (int j = 0; j < NN; j++) {
                #pragma unroll
                for (int g = 0; g < 4; g++)
                    MMA(acc[j][g], aM, bf[j][g * 2], bf[j][g * 2 + 1]);
                if (j == i) {
                    #pragma unroll
                    for (int g = 0; g < 4; g++)
                        MMA(acc[5][g], aW, bf[j][g * 2], bf[j][g * 2 + 1]);
                }
            }
        }
    }

    // ---- fused epilogue (accumulators in registers) ----
    const int tq = lane >> 2, tr = lane & 3;
    #pragma unroll
    for (int rh = 0; rh < 2; rh++) {
        const int o = o0 + wo + rh * 8 + tq;
        const float bv = bias[i * CC + o];
        #pragma unroll
        for (int g = 0; g < 4; g++) {
            const int p = p0 + wn + g * 8 + tr * 2;
            float2 xj[NN];
            #pragma unroll
            for (int j = 0; j < NN; j++)
                xj[j] = *(const float2*)(
                    x + ((size_t)((j * BB + b) * CC + o)) * HWD + p);
            float res[2];
            #pragma unroll
            for (int e = 0; e < 2; e++) {
                const float u = acc[5][g][rh * 2 + e] + bv;
                float ed[NN], m = 0.f;
                #pragma unroll
                for (int j = 0; j < NN; j++) {
                    float xv = e ? xj[j].y : xj[j].x;
                    float t = acc[j][g][rh * 2 + e] + u;
                    float d = fabsf(xv - t);
                    ed[j] = (d > 0.3f) ? d : 0.f;
                    m = fmaxf(m, ed[j]);
                }
                float sden = 0.f, a = 0.f;
                #pragma unroll
                for (int j = 0; j < NN; j++) {
                    float wgt = __expf(ed[j] - m);
                    sden += wgt;
                    a = fmaf(wgt, e ? xj[j].y : xj[j].x, a);
                }
                res[e] = a / sden;
            }
            *(float2*)(out + ((size_t)((i * BB + b) * CC + o)) * HWD + p) =
                make_float2(res[0], res[1]);
        }
    }
}

extern "C" void kernel_launch(void* const* d_in, const int* in_sizes, int n_in,
                              void* d_out, int out_size) {
    const float* x    = (const float*)d_in[0];   // [5,8,256,32,32]
    const float* w    = (const float*)d_in[1];   // [5,256,512]
    const float* bias = (const float*)d_in[2];   // [5,256]
    float* out = (float*)d_out;                  // [5,8,256,32,32]

    cudaFuncSetAttribute(fused_kernel,
                         cudaFuncAttributeMaxDynamicSharedMemorySize,
                         (int)sizeof(SmemT));

    prep_w<<<(NN * CC * KH + 255) / 256, 256>>>(w);
    prep_x<<<NN * BB * 8 * 8, 256>>>(x);
    // grid: x = b(8)*ptile(16) = 128, y = o-tiles(4), z = i(5)
    fused_kernel<<<dim3(128, 4, 5), THREADS, sizeof(SmemT)>>>(x, bias, out);
}

// round 8
// speedup vs baseline: 1.0634x; 1.0634x over previous
#include <cuda_runtime.h>
#include <cuda_bf16.h>

#define NN 5
#define BB 8
#define CC 256
#define HWD 1024
#define KH 512            // stored K per operand: [hi(256) | lo(256)]
#define NCH 12            // chunks: (Ahi,Bhi)x4, (Ahi,Blo)x4, (Alo,Bhi)x4
#define KC 64             // k per chunk
#define TM 64             // CTA o-tile
#define TPX 64            // CTA pixel-tile
#define THREADS 512
#define NSTG 3

// A operands [i][o][k2] (k2: 0-255 hi, 256-511 lo), k-contiguous
__device__ __align__(16) __nv_bfloat16 g_Am[NN * CC * KH];
__device__ __align__(16) __nv_bfloat16 g_Aw[NN * CC * KH];
// B operand  [j][b][p][k2], k-contiguous
__device__ __align__(16) __nv_bfloat16 g_X[NN * BB * HWD * KH];

__global__ void prep_w(const float* __restrict__ w) {
    int idx = blockIdx.x * blockDim.x + threadIdx.x;   // (i*CC+o)*KH + k2
    if (idx >= NN * CC * KH) return;
    int k2 = idx & (KH - 1);
    int oi = idx >> 9;
    int o = oi & 255, i = oi >> 8;
    int k = k2 & 255, lo = k2 >> 8;
    const float* row = w + (size_t)(i * CC + o) * (2 * CC);
    float w2 = row[CC + k];
    float m  = row[k] + w2;
    __nv_bfloat16 mh = __float2bfloat16_rn(m);
    __nv_bfloat16 wh = __float2bfloat16_rn(w2);
    g_Am[idx] = lo ? __float2bfloat16_rn(m  - __bfloat162float(mh)) : mh;
    g_Aw[idx] = lo ? __float2bfloat16_rn(w2 - __bfloat162float(wh)) : wh;
}

// Transpose [k][p] -> [p][k] with hi/lo split, via smem tile (32k x 128p).
__global__ __launch_bounds__(256) void prep_x(const float* __restrict__ x) {
    __shared__ float s[32][129];
    int bid = blockIdx.x;                      // jb(40) * ktile(8) * ptile(8)
    int pt = bid & 7, kt = (bid >> 3) & 7, jb = bid >> 6;
    int k0 = kt * 32, p0 = pt * 128;
    int tid = threadIdx.x;
    #pragma unroll
    for (int t = 0; t < 16; t++) {
        int idx = tid + t * 256;
        int kk = idx >> 7, pp = idx & 127;
        s[kk][pp] = x[((size_t)jb * CC + k0 + kk) * HWD + p0 + pp];
    }
    __syncthreads();
    int pp = tid & 127, part = tid >> 7;       // 0=hi, 1=lo
    __nv_bfloat16* dst = g_X + ((size_t)jb * HWD + p0 + pp) * KH + part * 256 + k0;
    #pragma unroll
    for (int kk = 0; kk < 32; kk += 2) {
        float v0 = s[kk][pp], v1 = s[kk + 1][pp];
        __nv_bfloat16 h0 = __float2bfloat16_rn(v0);
        __nv_bfloat16 h1 = __float2bfloat16_rn(v1);
        __nv_bfloat162 o2;
        if (part) {
            o2.x = __float2bfloat16_rn(v0 - __bfloat162float(h0));
            o2.y = __float2bfloat16_rn(v1 - __bfloat162float(h1));
        } else {
            o2.x = h0; o2.y = h1;
        }
        *(__nv_bfloat162*)(dst + kk) = o2;
    }
}

// ---- smem stage: A_M 8K | A_W 8K | B[5] 40K = 56KB; 3 stages = 168KB ----
#define STG 57344
#define OFF_AW 8192
#define OFF_B 16384
struct SmemT { char st[NSTG][STG]; };

#define LDM4(r, a) \
    asm volatile("ldmatrix.sync.aligned.m8n8.x4.shared.b16 {%0,%1,%2,%3}, [%4];" \
        : "=r"((r)[0]), "=r"((r)[1]), "=r"((r)[2]), "=r"((r)[3]) : "r"(a))

#define MMA(d, a, b0, b1) \
    asm volatile("mma.sync.aligned.m16n8k16.row.col.f32.bf16.bf16.f32 " \
        "{%0,%1,%2,%3}, {%4,%5,%6,%7}, {%8,%9}, {%0,%1,%2,%3};" \
        : "+f"((d)[0]), "+f"((d)[1]), "+f"((d)[2]), "+f"((d)[3]) \
        : "r"((a)[0]), "r"((a)[1]), "r"((a)[2]), "r"((a)[3]), "r"(b0), "r"(b1))

__global__ __launch_bounds__(THREADS, 1) void fused_kernel(
    const float* __restrict__ x,
    const float* __restrict__ bias,
    float* __restrict__ out)
{
    extern __shared__ __align__(16) char smem_raw[];
    SmemT& sm = *reinterpret_cast<SmemT*>(smem_raw);

    const int i  = blockIdx.z;
    const int o0 = blockIdx.y * TM;
    const int b  = blockIdx.x >> 4;
    const int p0 = (blockIdx.x & 15) * TPX;

    const int tid  = threadIdx.x;
    const int lane = tid & 31;
    const int wid  = tid >> 5;
    const int wo = (wid >> 2) * 16;            // warp o offset (0,16,32,48)
    const int wn = (wid & 3) * 16;             // warp px offset (0,16,32,48)
    const unsigned smem_base = (unsigned)__cvta_generic_to_shared(&sm);

    // ldmatrix geometry (swizzle XOR term = (lane&7)<<4 for all reads)
    const int sw7   = (lane & 7) << 4;
    const int arow  = wo + ((lane >> 3) & 1) * 8 + (lane & 7);
    const int a16   = (lane >> 4) * 16;        // A k-half byte offset
    const int brow  = wn + (lane >> 4) * 8 + (lane & 7);
    const int b16   = ((lane >> 3) & 1) * 16;  // B k-half byte offset

    // acc[mat][n8-group][reg]: mats 0-4 = v_j, 5 = u
    float acc[6][2][4];
    #pragma unroll
    for (int m = 0; m < 6; m++)
        #pragma unroll
        for (int g = 0; g < 2; g++)
            #pragma unroll
            for (int e = 0; e < 4; e++) acc[m][g][e] = 0.f;

    auto load_chunk = [&](int c, int s) {
        const int ka = (c < 8) ? (c & 3) * KC : 256 + (c - 8) * KC;
        const int kb = (c < 4) ? c * KC : (c < 8 ? 256 + (c - 4) * KC : (c - 8) * KC);
        char* stg = sm.st[s];
        #pragma unroll
        for (int t = 0; t < 7; t++) {
            int q = tid + t * THREADS;
            const __nv_bfloat16* src;
            int doff;
            if (q < 1024) {                      // A tiles
                int mat = q >> 9, idx = q & 511, row = idx >> 3, c16 = idx & 7;
                const __nv_bfloat16* g = mat ? g_Aw : g_Am;
                src = g + (size_t)(i * CC + o0 + row) * KH + ka + c16 * 8;
                doff = mat * OFF_AW + row * 128 + ((c16 << 4) ^ ((row & 7) << 4));
            } else {                             // B tiles: 5 x [64p][64k]
                int q2 = q - 1024;
                int j = q2 >> 9, idx = q2 & 511, row = idx >> 3, c16 = idx & 7;
                src = g_X + (size_t)((j * BB + b) * HWD + p0 + row) * KH + kb + c16 * 8;
                doff = OFF_B + j * 8192 + row * 128 + ((c16 << 4) ^ ((row & 7) << 4));
            }
            unsigned ds = (unsigned)__cvta_generic_to_shared(stg + doff);
            asm volatile("cp.async.cg.shared.global [%0], [%1], 16;"
                         :: "r"(ds), "l"(src));
        }
        asm volatile("cp.async.commit_group;");
    };

    load_chunk(0, 0);
    load_chunk(1, 1);

    int stage = 0;
    for (int c = 0; c < NCH; c++) {
        asm volatile("cp.async.wait_group 1;");   // chunk c complete
        __syncthreads();                          // all warps done with stage (c-1)%3
        if (c + 2 < NCH) {
            int s2 = stage + 2; if (s2 >= NSTG) s2 -= NSTG;
            load_chunk(c + 2, s2);                // overlaps compute of c, c+1
        }
        const unsigned stq = smem_base + (unsigned)(stage * STG);

        #pragma unroll
        for (int kk4 = 0; kk4 < 4; kk4++) {
            const int kko = kk4 * 32;             // k16-step byte offset
            unsigned aM[4], aW[4];
            {
                unsigned aa = stq + arow * 128 + (unsigned)((kko + a16) ^ sw7);
                LDM4(aM, aa);
                LDM4(aW, aa + OFF_AW);
            }
            unsigned bf[5][4];
            #pragma unroll
            for (int j = 0; j < NN; j++) {
                unsigned bb0 = stq + OFF_B + j * 8192 + brow * 128
                             + (unsigned)((kko + b16) ^ sw7);
                LDM4(bf[j], bb0);                 // 16px x 16k
            }
            #pragma unroll
            for (int j = 0; j < NN; j++) {
                MMA(acc[j][0], aM, bf[j][0], bf[j][1]);
                MMA(acc[j][1], aM, bf[j][2], bf[j][3]);
                if (j == i) {
                    MMA(acc[5][0], aW, bf[j][0], bf[j][1]);
                    MMA(acc[5][1], aW, bf[j][2], bf[j][3]);
                }
            }
        }
        if (++stage == NSTG) stage = 0;
    }

    // ---- fused epilogue (register accumulators) ----
    const int tq = lane >> 2, tr = lane & 3;
    #pragma unroll
    for (int rh = 0; rh < 2; rh++) {
        const int o = o0 + wo + rh * 8 + tq;
        const float bv = bias[i * CC + o];
        #pragma unroll
        for (int g = 0; g < 2; g++) {
            const int p = p0 + wn + g * 8 + tr * 2;
            float2 xj[NN];
            #pragma unroll
            for (int j = 0; j < NN; j++)
                xj[j] = *(const float2*)(
                    x + ((size_t)((j * BB + b) * CC + o)) * HWD + p);
            float res[2];
            #pragma unroll
            for (int e = 0; e < 2; e++) {
                const float u = acc[5][g][rh * 2 + e] + bv;
                float ed[NN], m = 0.f;
                #pragma unroll
                for (int j = 0; j < NN; j++) {
                    float xv = e ? xj[j].y : xj[j].x;
                    float t = acc[j][g][rh * 2 + e] + u;
                    float d = fabsf(xv - t);
                    ed[j] = (d > 0.3f) ? d : 0.f;
                    m = fmaxf(m, ed[j]);
                }
                float sden = 0.f, a = 0.f;
                #pragma unroll
                for (int j = 0; j < NN; j++) {
                    float wgt = __expf(ed[j] - m);
                    sden += wgt;
                    a = fmaf(wgt, e ? xj[j].y : xj[j].x, a);
                }
                res[e] = a / sden;
            }
            *(float2*)(out + ((size_t)((i * BB + b) * CC + o)) * HWD + p) =
                make_float2(res[0], res[1]);
        }
    }
}

extern "C" void kernel_launch(void* const* d_in, const int* in_sizes, int n_in,
                              void* d_out, int out_size) {
    const float* x    = (const float*)d_in[0];   // [5,8,256,32,32]
    const float* w    = (const float*)d_in[1];   // [5,256,512]
    const float* bias = (const float*)d_in[2];   // [5,256]
    float* out = (float*)d_out;                  // [5,8,256,32,32]

    cudaFuncSetAttribute(fused_kernel,
                         cudaFuncAttributeMaxDynamicSharedMemorySize,
                         (int)sizeof(SmemT));

    prep_w<<<(NN * CC * KH + 255) / 256, 256>>>(w);
    prep_x<<<NN * BB * 8 * 8, 256>>>(x);
    // grid: x = b(8)*ptile(16) = 128, y = o-tiles(4), z = i(5)
    fused_kernel<<<dim3(128, 4, 5), THREADS, sizeof(SmemT)>>>(x, bias, out);
}

// round 11
// speedup vs baseline: 1.5839x; 1.4895x over previous
#include <cuda_runtime.h>
#include <cuda_fp16.h>

#define NN 5
#define BB 8
#define CC 256
#define HWD 1024
#define KH 512            // stored K per operand: [hi(256) | lo(256)]
#define NCH 12            // 0-3:(Ahi,Bhi)f32acc  4-7:(Ahi,Blo)f16acc  8-11:(Alo,Bhi)f16acc
#define KC 64
#define TM 64
#define TPX 64
#define THREADS 512
#define NSTG 3
#define LSCALE 2048.0f    // 2^11 pre-scale on lo halves
#define LINV (1.0f / 2048.0f)

// A operands [i][o][k2] (k2: 0-255 hi, 256-511 lo*2^11), k-contiguous
__device__ __align__(16) __half g_Am[NN * CC * KH];
__device__ __align__(16) __half g_Aw[NN * CC * KH];
// B operand  [j][b][p][k2], k-contiguous
__device__ __align__(16) __half g_X[NN * BB * HWD * KH];

__global__ void prep_w(const float* __restrict__ w) {
    int idx = blockIdx.x * blockDim.x + threadIdx.x;   // (i*CC+o)*KH + k2
    if (idx >= NN * CC * KH) return;
    int k2 = idx & (KH - 1);
    int oi = idx >> 9;
    int o = oi & 255, i = oi >> 8;
    int k = k2 & 255, lo = k2 >> 8;
    const float* row = w + (size_t)(i * CC + o) * (2 * CC);
    float w2 = row[CC + k];
    float m  = row[k] + w2;
    __half mh = __float2half_rn(m);
    __half wh = __float2half_rn(w2);
    g_Am[idx] = lo ? __float2half_rn((m  - __half2float(mh)) * LSCALE) : mh;
    g_Aw[idx] = lo ? __float2half_rn((w2 - __half2float(wh)) * LSCALE) : wh;
}

// Transpose [k][p] -> [p][k] with hi/lo split, via smem tile (32k x 128p).
__global__ __launch_bounds__(256) void prep_x(const float* __restrict__ x) {
    __shared__ float s[32][129];
    int bid = blockIdx.x;                      // jb(40) * ktile(8) * ptile(8)
    int pt = bid & 7, kt = (bid >> 3) & 7, jb = bid >> 6;
    int k0 = kt * 32, p0 = pt * 128;
    int tid = threadIdx.x;
    #pragma unroll
    for (int t = 0; t < 16; t++) {
        int idx = tid + t * 256;
        int kk = idx >> 7, pp = idx & 127;
        s[kk][pp] = x[((size_t)jb * CC + k0 + kk) * HWD + p0 + pp];
    }
    __syncthreads();
    int pp = tid & 127, part = tid >> 7;       // 0=hi, 1=lo
    __half* dst = g_X + ((size_t)jb * HWD + p0 + pp) * KH + part * 256 + k0;
    #pragma unroll
    for (int kk = 0; kk < 32; kk += 2) {
        float v0 = s[kk][pp], v1 = s[kk + 1][pp];
        __half h0 = __float2half_rn(v0);
        __half h1 = __float2half_rn(v1);
        __half2 o2;
        if (part) {
            o2.x = __float2half_rn((v0 - __half2float(h0)) * LSCALE);
            o2.y = __float2half_rn((v1 - __half2float(h1)) * LSCALE);
        } else {
            o2.x = h0; o2.y = h1;
        }
        *(__half2*)(dst + kk) = o2;
    }
}

// ---- smem stage: A_M 8K | A_W 8K | B[5] 40K = 56KB; 3 stages = 168KB ----
#define STG 57344
#define OFF_AW 8192
#define OFF_B 16384
struct SmemT { char st[NSTG][STG]; };

#define LDM4(r, a) \
    asm volatile("ldmatrix.sync.aligned.m8n8.x4.shared.b16 {%0,%1,%2,%3}, [%4];" \
        : "=r"((r)[0]), "=r"((r)[1]), "=r"((r)[2]), "=r"((r)[3]) : "r"(a))

#define MMA32(d, a, b0, b1) \
    asm volatile("mma.sync.aligned.m16n8k16.row.col.f32.f16.f16.f32 " \
        "{%0,%1,%2,%3}, {%4,%5,%6,%7}, {%8,%9}, {%0,%1,%2,%3};" \
        : "+f"((d)[0]), "+f"((d)[1]), "+f"((d)[2]), "+f"((d)[3]) \
        : "r"((a)[0]), "r"((a)[1]), "r"((a)[2]), "r"((a)[3]), "r"(b0), "r"(b1))

#define MMA16(d, a, b0, b1) \
    asm volatile("mma.sync.aligned.m16n8k16.row.col.f16.f16.f16.f16 " \
        "{%0,%1}, {%2,%3,%4,%5}, {%6,%7}, {%0,%1};" \
        : "+r"((d)[0]), "+r"((d)[1]) \
        : "r"((a)[0]), "r"((a)[1]), "r"((a)[2]), "r"((a)[3]), "r"(b0), "r"(b1))

__global__ __launch_bounds__(THREADS, 1) void fused_kernel(
    const float* __restrict__ x,
    const float* __restrict__ bias,
    float* __restrict__ out)
{
    extern __shared__ __align__(16) char smem_raw[];
    SmemT& sm = *reinterpret_cast<SmemT*>(smem_raw);

    const int i  = blockIdx.z;
    const int o0 = blockIdx.y * TM;
    const int b  = blockIdx.x >> 4;
    const int p0 = (blockIdx.x & 15) * TPX;

    const int tid  = threadIdx.x;
    const int lane = tid & 31;
    const int wid  = tid >> 5;
    const int wo = (wid >> 2) * 16;            // warp o offset
    const int wn = (wid & 3) * 16;             // warp px offset
    const unsigned smem_base = (unsigned)__cvta_generic_to_shared(&sm);

    const int sw7   = (lane & 7) << 4;
    const int arow  = wo + ((lane >> 3) & 1) * 8 + (lane & 7);
    const int a16   = (lane >> 4) * 16;
    const int brow  = wn + (lane >> 4) * 8 + (lane & 7);
    const int b16   = ((lane >> 3) & 1) * 16;

    // main f32 acc: [mat][n8-group][4], corr f16 acc: [mat][n8-group][2 x f16x2]
    float acc[6][2][4];
    unsigned accC[6][2][2];
    #pragma unroll
    for (int m = 0; m < 6; m++)
        #pragma unroll
        for (int g = 0; g < 2; g++) {
            #pragma unroll
            for (int e = 0; e < 4; e++) acc[m][g][e] = 0.f;
            accC[m][g][0] = 0u; accC[m][g][1] = 0u;
        }

    auto load_chunk = [&](int c, int s) {
        const int ka = (c < 8) ? (c & 3) * KC : 256 + (c - 8) * KC;
        const int kb = (c < 4) ? c * KC : (c < 8 ? 256 + (c - 4) * KC : (c - 8) * KC);
        char* stg = sm.st[s];
        #pragma unroll
        for (int t = 0; t < 7; t++) {
            int q = tid + t * THREADS;
            const __half* src;
            int doff;
            if (q < 1024) {
                int mat = q >> 9, idx = q & 511, row = idx >> 3, c16 = idx & 7;
                const __half* g = mat ? g_Aw : g_Am;
                src = g + (size_t)(i * CC + o0 + row) * KH + ka + c16 * 8;
                doff = mat * OFF_AW + row * 128 + ((c16 << 4) ^ ((row & 7) << 4));
            } else {
                int q2 = q - 1024;
                int j = q2 >> 9, idx = q2 & 511, row = idx >> 3, c16 = idx & 7;
                src = g_X + (size_t)((j * BB + b) * HWD + p0 + row) * KH + kb + c16 * 8;
                doff = OFF_B + j * 8192 + row * 128 + ((c16 << 4) ^ ((row & 7) << 4));
            }
            unsigned ds = (unsigned)__cvta_generic_to_shared(stg + doff);
            asm volatile("cp.async.cg.shared.global [%0], [%1], 16;"
                         :: "r"(ds), "l"(src));
        }
        asm volatile("cp.async.commit_group;");
    };

    load_chunk(0, 0);
    load_chunk(1, 1);

    int stage = 0;
    for (int c = 0; c < NCH; c++) {
        asm volatile("cp.async.wait_group 1;");
        __syncthreads();
        if (c + 2 < NCH) {
            int s2 = stage + 2; if (s2 >= NSTG) s2 -= NSTG;
            load_chunk(c + 2, s2);
        }
        const unsigned stq = smem_base + (unsigned)(stage * STG);
        const bool main_chunk = (c < 4);

        #pragma unroll
        for (int kk4 = 0; kk4 < 4; kk4++) {
            const int kko = kk4 * 32;
            unsigned aM[4], aW[4];
            {
                unsigned aa = stq + arow * 128 + (unsigned)((kko + a16) ^ sw7);
                LDM4(aM, aa);
                LDM4(aW, aa + OFF_AW);
            }
            unsigned bf[5][4];
            #pragma unroll
            for (int j = 0; j < NN; j++) {
                unsigned bb0 = stq + OFF_B + j * 8192 + brow * 128
                             + (unsigned)((kko + b16) ^ sw7);
                LDM4(bf[j], bb0);
            }
            if (main_chunk) {
                #pragma unroll
                for (int j = 0; j < NN; j++) {
                    MMA32(acc[j][0], aM, bf[j][0], bf[j][1]);
                    MMA32(acc[j][1], aM, bf[j][2], bf[j][3]);
                    if (j == i) {
                        MMA32(acc[5][0], aW, bf[j][0], bf[j][1]);
                        MMA32(acc[5][1], aW, bf[j][2], bf[j][3]);
                    }
                }
            } else {
                #pragma unroll
                for (int j = 0; j < NN; j++) {
                    MMA16(accC[j][0], aM, bf[j][0], bf[j][1]);
                    MMA16(accC[j][1], aM, bf[j][2], bf[j][3]);
                    if (j == i) {
                        MMA16(accC[5][0], aW, bf[j][0], bf[j][1]);
                        MMA16(accC[5][1], aW, bf[j][2], bf[j][3]);
                    }
                }
            }
        }
        if (++stage == NSTG) stage = 0;
    }

    // ---- fused epilogue: t = main + corr*2^-11 + bias; edge/softmax/aggregate ----
    const int tq = lane >> 2, tr = lane & 3;
    #pragma unroll
    for (int rh = 0; rh < 2; rh++) {
        const int o = o0 + wo + rh * 8 + tq;
        const float bv = bias[i * CC + o];
        #pragma unroll
        for (int g = 0; g < 2; g++) {
            const int p = p0 + wn + g * 8 + tr * 2;
            float2 xj[NN];
            #pragma unroll
            for (int j = 0; j < NN; j++)
                xj[j] = *(const float2*)(
                    x + ((size_t)((j * BB + b) * CC + o)) * HWD + p);
            // corrections for this rh: one f16x2 per mat
            float2 cor[6];
            #pragma unroll
            for (int m = 0; m < 6; m++)
                cor[m] = __half22float2(*(__half2*)&accC[m][g][rh]);
            float res[2];
            #pragma unroll
            for (int e = 0; e < 2; e++) {
                const float cu = e ? cor[5].y : cor[5].x;
                const float u = acc[5][g][rh * 2 + e] + cu * LINV + bv;
                float ed[NN], m2 = 0.f;
                #pragma unroll
                for (int j = 0; j < NN; j++) {
                    float xv = e ? xj[j].y : xj[j].x;
                    float cj = e ? cor[j].y : cor[j].x;
                    float t = acc[j][g][rh * 2 + e] + cj * LINV + u;
                    float d = fabsf(xv - t);
                    ed[j] = (d > 0.3f) ? d : 0.f;
                    m2 = fmaxf(m2, ed[j]);
                }
                float sden = 0.f, a = 0.f;
                #pragma unroll
                for (int j = 0; j < NN; j++) {
                    float wgt = __expf(ed[j] - m2);
                    sden += wgt;
                    a = fmaf(wgt, e ? xj[j].y : xj[j].x, a);
                }
                res[e] = a / sden;
            }
            *(float2*)(out + ((size_t)((i * BB + b) * CC + o)) * HWD + p) =
                make_float2(res[0], res[1]);
        }
    }
}

extern "C" void kernel_launch(void* const* d_in, const int* in_sizes, int n_in,
                              void* d_out, int out_size) {
    const float* x    = (const float*)d_in[0];   // [5,8,256,32,32]
    const float* w    = (const float*)d_in[1];   // [5,256,512]
    const float* bias = (const float*)d_in[2];   // [5,256]
    float* out = (float*)d_out;                  // [5,8,256,32,32]

    cudaFuncSetAttribute(fused_kernel,
                         cudaFuncAttributeMaxDynamicSharedMemorySize,
                         (int)sizeof(SmemT));

    prep_w<<<(NN * CC * KH + 255) / 256, 256>>>(w);
    prep_x<<<NN * BB * 8 * 8, 256>>>(x);
    fused_kernel<<<dim3(128, 4, 5), THREADS, sizeof(SmemT)>>>(x, bias, out);
}